// round 1
// baseline (speedup 1.0000x reference)
#include <cuda_runtime.h>
#include <math.h>

#define DINL __device__ __forceinline__

// ----------------------------- scratch ------------------------------------
struct Scalars {
  int   xabs_bits;
  int   max1, max2;
  float s_in, sw1, sw2, swf1, swf2;
  float S1;        // s_in*sw1
  float s1, f1;    // f1 = 15*S1 / max(max1*S1,1e-8)
  float S2;        // s1*sw2
  float s2, r2;    // r2 = 15*S2 / max(max2*S2,1e-8)
};
__device__ Scalars g_s;
__device__ int g_xabsarr[256];
__device__ int g_max1arr[256];
__device__ int g_max2arr[256];

__device__ __align__(16) unsigned       g_qx [32 * 224 * 224];       // [b][h][w] 4-ch packed (c0,c1,c2,0)
__device__ __align__(16) short          g_y1 [32u * 222 * 222 * 32]; // NHWC int16 conv1 pre-quant
__device__ __align__(16) unsigned char  g_q1 [32u * 222 * 222 * 32]; // NHWC u8 (0..15)
__device__ __align__(16) int            g_y2 [32u * 64 * 220 * 220]; // NCHW int32 conv2 pre-quant
__device__ int      g_pool[32 * 64];
__device__ __align__(16) unsigned g_w1p[9 * 32];      // [tap][oc]  bytes: ic0,ic1,ic2,0
__device__ __align__(16) unsigned g_w2p[9 * 8 * 64];  // [(tap*8+cc)][oc] bytes: 4 ic of chunk cc
__device__ signed char g_wf1q[128 * 64];
__device__ signed char g_wf2q[10 * 128];
__device__ int g_b1i[32];
__device__ int g_b2i[64];

// ----------------------------- helpers ------------------------------------
DINL int clamp_i(int v, int lo, int hi) { return v < lo ? lo : (v > hi ? hi : v); }

DINL float blockMax256(float v, float* smax) {   // blockDim.x == 256
  #pragma unroll
  for (int o = 16; o; o >>= 1) v = fmaxf(v, __shfl_xor_sync(0xffffffffu, v, o));
  if ((threadIdx.x & 31) == 0) smax[threadIdx.x >> 5] = v;
  __syncthreads();
  if (threadIdx.x == 0) {
    float r = smax[0];
    #pragma unroll
    for (int i = 1; i < 8; i++) r = fmaxf(r, smax[i]);
    smax[0] = r;
  }
  __syncthreads();
  float r = smax[0];
  __syncthreads();
  return r;
}

DINL void blockAtomicMaxInt(int v, int* dst) {   // blockDim.x == 256
  v = __reduce_max_sync(0xffffffffu, v);
  __shared__ int smx[8];
  if ((threadIdx.x & 31) == 0) smx[threadIdx.x >> 5] = v;
  __syncthreads();
  if (threadIdx.x == 0) {
    int m = smx[0];
    #pragma unroll
    for (int i = 1; i < 8; i++) m = max(m, smx[i]);
    atomicMax(dst, m);
  }
}

// ----------------------------- K0: init -----------------------------------
__global__ void k_init() {
  int t = threadIdx.x;
  if (t < 256) { g_xabsarr[t] = 0; g_max1arr[t] = 0; g_max2arr[t] = 0; }
  if (t == 0) { g_s.xabs_bits = 0; g_s.max1 = 0; g_s.max2 = 0; }
}

// ----------------------------- K1: |x| max --------------------------------
__global__ void k_absmax_x(const float* __restrict__ x, int n) {
  float m = 0.f;
  for (int i = blockIdx.x * blockDim.x + threadIdx.x; i < n; i += gridDim.x * blockDim.x)
    m = fmaxf(m, fabsf(x[i]));
  #pragma unroll
  for (int o = 16; o; o >>= 1) m = fmaxf(m, __shfl_xor_sync(0xffffffffu, m, o));
  __shared__ float sm[8];
  if ((threadIdx.x & 31) == 0) sm[threadIdx.x >> 5] = m;
  __syncthreads();
  if (threadIdx.x == 0) {
    float r = sm[0];
    #pragma unroll
    for (int i = 1; i < 8; i++) r = fmaxf(r, sm[i]);
    atomicMax(&g_xabsarr[blockIdx.x & 255], __float_as_int(r));
  }
}

// ---------------- K2: weight maxes, scales, quantize+pack weights ----------
__global__ void k_prep(const float* __restrict__ w1, const float* __restrict__ b1,
                       const float* __restrict__ w2,
                       const float* __restrict__ wf1, const float* __restrict__ wf2) {
  __shared__ float smax[8];
  __shared__ float sc[8];
  const int t = threadIdx.x;

  float mx = blockMax256(__int_as_float(g_xabsarr[t]), smax);

  float m = 0.f;
  for (int i = t; i < 32 * 3 * 3 * 3; i += 256) m = fmaxf(m, fabsf(w1[i]));
  float mw1 = blockMax256(m, smax);

  m = 0.f;
  for (int i = t; i < 64 * 32 * 3 * 3; i += 256) m = fmaxf(m, fabsf(w2[i]));
  float mw2 = blockMax256(m, smax);

  m = 0.f;
  for (int i = t; i < 128 * 64; i += 256) m = fmaxf(m, fabsf(wf1[i]));
  float mf1 = blockMax256(m, smax);

  m = 0.f;
  for (int i = t; i < 10 * 128; i += 256) m = fmaxf(m, fabsf(wf2[i]));
  float mf2 = blockMax256(m, smax);

  if (t == 0) {
    float s_in = fmaxf(mx, 1e-8f) / 7.0f;
    float sw1  = fmaxf(mw1, 1e-8f) / 7.0f;
    float sw2  = fmaxf(mw2, 1e-8f) / 7.0f;
    float swf1 = fmaxf(mf1, 1e-8f) / 7.0f;
    float swf2 = fmaxf(mf2, 1e-8f) / 7.0f;
    g_s.s_in = s_in; g_s.sw1 = sw1; g_s.sw2 = sw2; g_s.swf1 = swf1; g_s.swf2 = swf2;
    g_s.S1 = s_in * sw1;
    sc[0] = s_in; sc[1] = sw1; sc[2] = sw2; sc[3] = swf1; sc[4] = swf2;
  }
  __syncthreads();
  const float s_in = sc[0], sw1 = sc[1], sw2 = sc[2], swf1 = sc[3], swf2 = sc[4];

  // w1 packed: [tap][oc], bytes = ic0..ic2, 0
  for (int i = t; i < 9 * 32; i += 256) {
    int tap = i / 32, oc = i % 32, kh = tap / 3, kw = tap % 3;
    unsigned v = 0;
    #pragma unroll
    for (int c = 0; c < 3; c++) {
      int q = clamp_i((int)rintf(w1[((oc * 3 + c) * 3 + kh) * 3 + kw] / sw1), -8, 7);
      v |= ((unsigned)(q & 0xff)) << (8 * c);
    }
    g_w1p[i] = v;
  }
  for (int i = t; i < 32; i += 256) g_b1i[i] = (int)rintf(b1[i] / (s_in * sw1));

  // w2 packed: [(tap*8+cc)][oc], bytes = ic cc*4..cc*4+3
  for (int i = t; i < 9 * 8 * 64; i += 256) {
    int oc = i & 63, tc = i >> 6, tap = tc >> 3, cc = tc & 7;
    int kh = tap / 3, kw = tap % 3;
    unsigned v = 0;
    #pragma unroll
    for (int j = 0; j < 4; j++) {
      int ic = cc * 4 + j;
      int q = clamp_i((int)rintf(w2[((oc * 32 + ic) * 3 + kh) * 3 + kw] / sw2), -8, 7);
      v |= ((unsigned)(q & 0xff)) << (8 * j);
    }
    g_w2p[i] = v;
  }
  for (int i = t; i < 128 * 64; i += 256)
    g_wf1q[i] = (signed char)clamp_i((int)rintf(wf1[i] / swf1), -8, 7);
  for (int i = t; i < 10 * 128; i += 256)
    g_wf2q[i] = (signed char)clamp_i((int)rintf(wf2[i] / swf2), -8, 7);
}

// ----------------- K3: quantize x -> NHWC4 packed int8 ---------------------
__global__ void k_quant_x(const float* __restrict__ x) {
  int i = blockIdx.x * blockDim.x + threadIdx.x;
  if (i >= 32 * 224 * 224) return;
  int b = i / 50176, hw = i % 50176;
  float s = g_s.s_in;
  unsigned v = 0;
  #pragma unroll
  for (int c = 0; c < 3; c++) {
    float xv = x[(b * 3 + c) * 50176 + hw];
    int q = clamp_i((int)rintf(xv / s), -8, 7);
    v |= ((unsigned)(q & 0xff)) << (8 * c);
  }
  g_qx[i] = v;
}

// ----------------- K4: conv1 (int8 dp4a) -> y1 int16 NHWC + relu max -------
__global__ void __launch_bounds__(256) k_conv1() {
  __shared__ int   s_in[340];     // [10 rows][34 cols]
  __shared__ uint4 s_w[18];       // [tap][2] : 8 oc per block
  const int bz = blockIdx.z;
  const int b = bz >> 2, ocg = bz & 3;
  const int h0 = blockIdx.y * 8, w0 = blockIdx.x * 32;
  const int t = threadIdx.x;

  if (t < 18)
    s_w[t] = *(const uint4*)&g_w1p[(t >> 1) * 32 + ocg * 8 + (t & 1) * 4];
  for (int i = t; i < 340; i += 256) {
    int row = i / 34, col = i % 34;
    int h = h0 + row, w = w0 + col;
    int v = 0;
    if (h < 224 && w < 224) v = (int)g_qx[(b * 224 + h) * 224 + w];
    s_in[i] = v;
  }
  __syncthreads();

  const int ty = t >> 5, tx = t & 31;
  int acc[8];
  #pragma unroll
  for (int k = 0; k < 8; k++) acc[k] = g_b1i[ocg * 8 + k];

  #pragma unroll
  for (int kh = 0; kh < 3; kh++) {
    #pragma unroll
    for (int kw = 0; kw < 3; kw++) {
      int a = s_in[(ty + kh) * 34 + tx + kw];
      uint4 wa = s_w[(kh * 3 + kw) * 2];
      uint4 wb = s_w[(kh * 3 + kw) * 2 + 1];
      acc[0] = __dp4a(a, (int)wa.x, acc[0]);
      acc[1] = __dp4a(a, (int)wa.y, acc[1]);
      acc[2] = __dp4a(a, (int)wa.z, acc[2]);
      acc[3] = __dp4a(a, (int)wa.w, acc[3]);
      acc[4] = __dp4a(a, (int)wb.x, acc[4]);
      acc[5] = __dp4a(a, (int)wb.y, acc[5]);
      acc[6] = __dp4a(a, (int)wb.z, acc[6]);
      acc[7] = __dp4a(a, (int)wb.w, acc[7]);
    }
  }

  const int oh = h0 + ty, ow = w0 + tx;
  int mloc = 0;
  if (oh < 222 && ow < 222) {
    unsigned p0 = (acc[0] & 0xffff) | ((unsigned)acc[1] << 16);
    unsigned p1 = (acc[2] & 0xffff) | ((unsigned)acc[3] << 16);
    unsigned p2 = (acc[4] & 0xffff) | ((unsigned)acc[5] << 16);
    unsigned p3 = (acc[6] & 0xffff) | ((unsigned)acc[7] << 16);
    *(uint4*)&g_y1[(size_t)((b * 222 + oh) * 222 + ow) * 32 + ocg * 8] = make_uint4(p0, p1, p2, p3);
    #pragma unroll
    for (int k = 0; k < 8; k++) mloc = max(mloc, acc[k]);
  }
  int lb = (blockIdx.x + 7 * (blockIdx.y + 28 * blockIdx.z)) & 255;
  blockAtomicMaxInt(mloc, &g_max1arr[lb]);
}

// ----------------- K5: reduce max1, s1/f1/S2, b2 int -----------------------
__global__ void k_scales1(const float* __restrict__ b2) {
  const int t = threadIdx.x;
  int v = g_max1arr[t];
  v = __reduce_max_sync(0xffffffffu, v);
  __shared__ int   smx[8];
  __shared__ float sc[2];
  if ((t & 31) == 0) smx[t >> 5] = v;
  __syncthreads();
  if (t == 0) {
    int mm = smx[0];
    #pragma unroll
    for (int i = 1; i < 8; i++) mm = max(mm, smx[i]);
    float S1 = g_s.S1;
    float my = fmaxf((float)mm * S1, 1e-8f);
    float s1 = my / 15.0f;
    g_s.max1 = mm;
    g_s.s1 = s1;
    g_s.f1 = 15.0f * S1 / my;
    float S2 = s1 * g_s.sw2;
    g_s.S2 = S2;
    sc[0] = s1; sc[1] = g_s.sw2;
  }
  __syncthreads();
  if (t < 64) g_b2i[t] = (int)rintf(b2[t] / (sc[0] * sc[1]));
}

// ----------------- K6: quantize y1 -> q1 u8 (0..15) ------------------------
__global__ void k_quant_y1() {
  unsigned i = blockIdx.x * blockDim.x + threadIdx.x;   // one thread = 8 values
  if (i >= 50466816u / 8u) return;
  const float f1 = g_s.f1;
  uint4 v = ((const uint4*)g_y1)[i];
  int a0 = (short)(v.x & 0xffff), a1 = (short)(v.x >> 16);
  int a2 = (short)(v.y & 0xffff), a3 = (short)(v.y >> 16);
  int a4 = (short)(v.z & 0xffff), a5 = (short)(v.z >> 16);
  int a6 = (short)(v.w & 0xffff), a7 = (short)(v.w >> 16);
  unsigned q0 = (unsigned)clamp_i((int)rintf((float)a0 * f1), 0, 15);
  unsigned q1 = (unsigned)clamp_i((int)rintf((float)a1 * f1), 0, 15);
  unsigned q2 = (unsigned)clamp_i((int)rintf((float)a2 * f1), 0, 15);
  unsigned q3 = (unsigned)clamp_i((int)rintf((float)a3 * f1), 0, 15);
  unsigned q4 = (unsigned)clamp_i((int)rintf((float)a4 * f1), 0, 15);
  unsigned q5 = (unsigned)clamp_i((int)rintf((float)a5 * f1), 0, 15);
  unsigned q6 = (unsigned)clamp_i((int)rintf((float)a6 * f1), 0, 15);
  unsigned q7 = (unsigned)clamp_i((int)rintf((float)a7 * f1), 0, 15);
  ((uint2*)g_q1)[i] = make_uint2(q0 | (q1 << 8) | (q2 << 16) | (q3 << 24),
                                 q4 | (q5 << 8) | (q6 << 16) | (q7 << 24));
}

// ----------------- K7: conv2 (int8 dp4a) -> y2 int32 NCHW + relu max -------
__global__ void __launch_bounds__(256) k_conv2() {
  __shared__ int   s_in[8][340];   // channel-major: conflict-free reads
  __shared__ uint4 s_w[144];       // [(tap*8+cc)][2] : 8 oc per block
  const int bz = blockIdx.z;
  const int b = bz >> 3, ocg = bz & 7;
  const int h0 = blockIdx.y * 8, w0 = blockIdx.x * 32;
  const int t = threadIdx.x;

  for (int i = t; i < 144; i += 256)
    s_w[i] = *(const uint4*)&g_w2p[(i >> 1) * 64 + ocg * 8 + (i & 1) * 4];

  const unsigned* q1u = (const unsigned*)g_q1;
  for (int i = t; i < 2720; i += 256) {
    int cc = i & 7;
    int col = (i >> 3) % 34;
    int row = i / 272;
    int h = h0 + row, w = w0 + col;
    int v = 0;
    if (h < 222 && w < 222) v = (int)q1u[((b * 222 + h) * 222 + w) * 8 + cc];
    s_in[cc][row * 34 + col] = v;
  }
  __syncthreads();

  const int ty = t >> 5, tx = t & 31;
  int acc[8];
  #pragma unroll
  for (int k = 0; k < 8; k++) acc[k] = g_b2i[ocg * 8 + k];

  #pragma unroll
  for (int kh = 0; kh < 3; kh++) {
    #pragma unroll
    for (int kw = 0; kw < 3; kw++) {
      const int pix = (ty + kh) * 34 + tx + kw;
      const int tap = kh * 3 + kw;
      #pragma unroll
      for (int cc = 0; cc < 8; cc++) {
        int a = s_in[cc][pix];
        uint4 wa = s_w[(tap * 8 + cc) * 2];
        uint4 wb = s_w[(tap * 8 + cc) * 2 + 1];
        acc[0] = __dp4a(a, (int)wa.x, acc[0]);
        acc[1] = __dp4a(a, (int)wa.y, acc[1]);
        acc[2] = __dp4a(a, (int)wa.z, acc[2]);
        acc[3] = __dp4a(a, (int)wa.w, acc[3]);
        acc[4] = __dp4a(a, (int)wb.x, acc[4]);
        acc[5] = __dp4a(a, (int)wb.y, acc[5]);
        acc[6] = __dp4a(a, (int)wb.z, acc[6]);
        acc[7] = __dp4a(a, (int)wb.w, acc[7]);
      }
    }
  }

  const int oh = h0 + ty, ow = w0 + tx;
  int mloc = 0;
  if (oh < 220 && ow < 220) {
    int base = (b * 64 + ocg * 8) * 48400 + oh * 220 + ow;
    #pragma unroll
    for (int k = 0; k < 8; k++) {
      g_y2[base + k * 48400] = acc[k];
      mloc = max(mloc, acc[k]);
    }
  }
  int lb = (blockIdx.x + 7 * (blockIdx.y + 28 * blockIdx.z)) & 255;
  blockAtomicMaxInt(mloc, &g_max2arr[lb]);
}

// ----------------- K7.5: reduce max2, s2/r2 --------------------------------
__global__ void k_scales2() {
  const int t = threadIdx.x;
  int v = g_max2arr[t];
  v = __reduce_max_sync(0xffffffffu, v);
  __shared__ int smx[8];
  if ((t & 31) == 0) smx[t >> 5] = v;
  __syncthreads();
  if (t == 0) {
    int mm = smx[0];
    #pragma unroll
    for (int i = 1; i < 8; i++) mm = max(mm, smx[i]);
    float S2 = g_s.S2;
    float my = fmaxf((float)mm * S2, 1e-8f);
    g_s.max2 = mm;
    g_s.s2 = my / 15.0f;
    g_s.r2 = 15.0f * S2 / my;
  }
}

// ----------------- K8: quantize y2 + avg-pool (int sums) -------------------
__global__ void __launch_bounds__(256) k_pool() {
  const int bc = blockIdx.x;                 // b*64 + c
  const int* __restrict__ p = g_y2 + (size_t)bc * 48400;
  const float r2 = g_s.r2;
  int s = 0;
  for (int i = threadIdx.x; i < 48400; i += 256) {
    int q = clamp_i((int)rintf((float)p[i] * r2), 0, 15);
    s += q;
  }
  s = __reduce_add_sync(0xffffffffu, s);
  __shared__ int sm[8];
  if ((threadIdx.x & 31) == 0) sm[threadIdx.x >> 5] = s;
  __syncthreads();
  if (threadIdx.x == 0) {
    int r = 0;
    #pragma unroll
    for (int i = 0; i < 8; i++) r += sm[i];
    g_pool[bc] = r;
  }
}

// ----------------- K9: head (mean, fc1, relu4, fc2, log_softmax) -----------
__global__ void __launch_bounds__(256) k_head(const float* __restrict__ bf1,
                                              const float* __restrict__ bf2,
                                              float* __restrict__ out) {
  __shared__ float mean[32 * 64];
  __shared__ float y3[32 * 128];
  __shared__ float y4[320];
  __shared__ float red[8];
  __shared__ float s3sh;
  const int t = threadIdx.x;

  const float s2 = g_s.s2;
  const float swf1 = g_s.swf1, swf2 = g_s.swf2;
  const float msc = s2 / 48400.0f;
  for (int i = t; i < 2048; i += 256) mean[i] = (float)g_pool[i] * msc;
  __syncthreads();

  float lmax = 0.f;
  for (int idx = t; idx < 4096; idx += 256) {
    int b = idx >> 7, o = idx & 127;
    const signed char* wr = &g_wf1q[o * 64];
    const float* mr = &mean[b * 64];
    float a = 0.f;
    #pragma unroll 8
    for (int c = 0; c < 64; c++) a += mr[c] * (float)wr[c];
    float bq = rintf(bf1[o] / (s2 * swf1)) * (s2 * swf1);
    float y = swf1 * a + bq;
    y3[idx] = y;
    lmax = fmaxf(lmax, y);
  }
  #pragma unroll
  for (int o = 16; o; o >>= 1) lmax = fmaxf(lmax, __shfl_xor_sync(0xffffffffu, lmax, o));
  if ((t & 31) == 0) red[t >> 5] = lmax;
  __syncthreads();
  if (t == 0) {
    float r = red[0];
    #pragma unroll
    for (int i = 1; i < 8; i++) r = fmaxf(r, red[i]);
    s3sh = fmaxf(r, 1e-8f) / 15.0f;
  }
  __syncthreads();
  const float s3 = s3sh;

  for (int idx = t; idx < 320; idx += 256) {
    int b = idx / 10, k = idx % 10;
    const signed char* wr = &g_wf2q[k * 128];
    const float* yr = &y3[b * 128];
    float a = 0.f;
    #pragma unroll 8
    for (int o = 0; o < 128; o++) {
      int q = clamp_i((int)rintf(yr[o] / s3), 0, 15);
      a += (float)q * (float)wr[o];
    }
    float bq = rintf(bf2[k] / (s3 * swf2)) * (s3 * swf2);
    y4[idx] = s3 * swf2 * a + bq;
  }
  __syncthreads();

  if (t < 32) {
    float mval = -1e30f;
    #pragma unroll
    for (int k = 0; k < 10; k++) mval = fmaxf(mval, y4[t * 10 + k]);
    float ssum = 0.f;
    #pragma unroll
    for (int k = 0; k < 10; k++) ssum += expf(y4[t * 10 + k] - mval);
    float l = logf(ssum);
    #pragma unroll
    for (int k = 0; k < 10; k++) out[t * 10 + k] = y4[t * 10 + k] - mval - l;
  }
}

// ----------------------------- launcher ------------------------------------
extern "C" void kernel_launch(void* const* d_in, const int* in_sizes, int n_in,
                              void* d_out, int out_size) {
  const float* x   = (const float*)d_in[0];
  const float* w1  = (const float*)d_in[1];
  const float* b1  = (const float*)d_in[2];
  const float* w2  = (const float*)d_in[3];
  const float* b2  = (const float*)d_in[4];
  const float* wf1 = (const float*)d_in[5];
  const float* bf1 = (const float*)d_in[6];
  const float* wf2 = (const float*)d_in[7];
  const float* bf2 = (const float*)d_in[8];
  float* out = (float*)d_out;

  k_init<<<1, 256>>>();
  k_absmax_x<<<2048, 256>>>(x, 32 * 3 * 224 * 224);
  k_prep<<<1, 256>>>(w1, b1, w2, wf1, wf2);
  k_quant_x<<<(32 * 224 * 224 + 255) / 256, 256>>>(x);
  k_conv1<<<dim3(7, 28, 128), 256>>>();
  k_scales1<<<1, 256>>>(b2);
  k_quant_y1<<<(50466816 / 8 + 255) / 256, 256>>>();
  k_conv2<<<dim3(7, 28, 256), 256>>>();
  k_scales2<<<1, 256>>>();
  k_pool<<<2048, 256>>>();
  k_head<<<1, 256>>>(bf1, bf2, out);
}

// round 5
// speedup vs baseline: 1.4602x; 1.4602x over previous
#include <cuda_runtime.h>
#include <cuda_fp16.h>
#include <math.h>
#include <stdint.h>

#define DINL __device__ __forceinline__

// ============================== scratch ====================================
struct Scalars {
  int   max1;
  float s_in, sw1, sw2, swf1, swf2;
  float S1, s1, f1, S2, s2, r2;
};
__device__ Scalars g_s;
__device__ int g_xabsarr[256];
__device__ int g_max1arr[256];
__device__ int g_max2arr[256];   // float bits (nonneg)

__device__ __align__(16) unsigned g_qx [32 * 224 * 224];       // packed s8 x,y,z ch
__device__ __align__(16) short    g_y1 [32u * 222 * 222 * 32]; // conv1 int16 NHWC
__device__ __align__(16) __half   g_q1h[32u * 222 * 222 * 32]; // relu4-quant fp16 NHWC
__device__ __align__(16) __half   g_y2h[32u * 64 * 220 * 220]; // conv2 out fp16 NCHW
__device__ int g_pool[32 * 64];
__device__ __align__(16) unsigned g_w1p[9 * 32];
__device__ __align__(16) uint2    g_w2frag[8 * 18 * 32];       // [n][? k*8+n][lane] mma B frags fp16
__device__ signed char g_wf1q[128 * 64];
__device__ signed char g_wf2q[10 * 128];
__device__ int g_b1i[32];
__device__ int g_b2i[64];

// ============================== helpers ====================================
DINL int clamp_i(int v, int lo, int hi) { return v < lo ? lo : (v > hi ? hi : v); }

DINL float blockMax256(float v, float* smax) {
  #pragma unroll
  for (int o = 16; o; o >>= 1) v = fmaxf(v, __shfl_xor_sync(0xffffffffu, v, o));
  if ((threadIdx.x & 31) == 0) smax[threadIdx.x >> 5] = v;
  __syncthreads();
  if (threadIdx.x == 0) {
    float r = smax[0];
    #pragma unroll
    for (int i = 1; i < 8; i++) r = fmaxf(r, smax[i]);
    smax[0] = r;
  }
  __syncthreads();
  float r = smax[0];
  __syncthreads();
  return r;
}

// ============================== K0: init ===================================
__global__ void k_init() {
  int t = threadIdx.x;
  if (t < 256) { g_xabsarr[t] = 0; g_max1arr[t] = 0; g_max2arr[t] = 0; }
  if (t == 0) { g_s.max1 = 0; }
}

// ============================== K1: |x| max ================================
__global__ void k_absmax_x(const float* __restrict__ x, int n) {
  float m = 0.f;
  for (int i = blockIdx.x * blockDim.x + threadIdx.x; i < n; i += gridDim.x * blockDim.x)
    m = fmaxf(m, fabsf(x[i]));
  #pragma unroll
  for (int o = 16; o; o >>= 1) m = fmaxf(m, __shfl_xor_sync(0xffffffffu, m, o));
  __shared__ float sm[8];
  if ((threadIdx.x & 31) == 0) sm[threadIdx.x >> 5] = m;
  __syncthreads();
  if (threadIdx.x == 0) {
    float r = sm[0];
    #pragma unroll
    for (int i = 1; i < 8; i++) r = fmaxf(r, sm[i]);
    atomicMax(&g_xabsarr[blockIdx.x & 255], __float_as_int(r));
  }
}

// ============ K2: weight maxes, scales, quantize + pack weights ============
__global__ void k_prep(const float* __restrict__ w1, const float* __restrict__ b1,
                       const float* __restrict__ w2,
                       const float* __restrict__ wf1, const float* __restrict__ wf2) {
  __shared__ float smax[8];
  __shared__ float sc[8];
  const int t = threadIdx.x;

  float mx = blockMax256(__int_as_float(g_xabsarr[t]), smax);

  float m = 0.f;
  for (int i = t; i < 32 * 3 * 3 * 3; i += 256) m = fmaxf(m, fabsf(w1[i]));
  float mw1 = blockMax256(m, smax);
  m = 0.f;
  for (int i = t; i < 64 * 32 * 3 * 3; i += 256) m = fmaxf(m, fabsf(w2[i]));
  float mw2 = blockMax256(m, smax);
  m = 0.f;
  for (int i = t; i < 128 * 64; i += 256) m = fmaxf(m, fabsf(wf1[i]));
  float mf1 = blockMax256(m, smax);
  m = 0.f;
  for (int i = t; i < 10 * 128; i += 256) m = fmaxf(m, fabsf(wf2[i]));
  float mf2 = blockMax256(m, smax);

  if (t == 0) {
    float s_in = fmaxf(mx, 1e-8f) / 7.0f;
    float sw1  = fmaxf(mw1, 1e-8f) / 7.0f;
    float sw2  = fmaxf(mw2, 1e-8f) / 7.0f;
    float swf1 = fmaxf(mf1, 1e-8f) / 7.0f;
    float swf2 = fmaxf(mf2, 1e-8f) / 7.0f;
    g_s.s_in = s_in; g_s.sw1 = sw1; g_s.sw2 = sw2; g_s.swf1 = swf1; g_s.swf2 = swf2;
    g_s.S1 = s_in * sw1;
    sc[0] = s_in; sc[1] = sw1; sc[2] = sw2; sc[3] = swf1; sc[4] = swf2;
  }
  __syncthreads();
  const float s_in = sc[0], sw1 = sc[1], sw2 = sc[2], swf1 = sc[3], swf2 = sc[4];

  for (int i = t; i < 9 * 32; i += 256) {
    int tap = i / 32, oc = i % 32, kh = tap / 3, kw = tap % 3;
    unsigned v = 0;
    #pragma unroll
    for (int c = 0; c < 3; c++) {
      int q = clamp_i((int)rintf(w1[((oc * 3 + c) * 3 + kh) * 3 + kw] / sw1), -8, 7);
      v |= ((unsigned)(q & 0xff)) << (8 * c);
    }
    g_w1p[i] = v;
  }
  for (int i = t; i < 32; i += 256) g_b1i[i] = (int)rintf(b1[i] / (s_in * sw1));

  // w2 -> fp16 mma B fragments: idx = (k_chunk*8 + n_chunk)*32 + lane
  // b0 = K rows (k*16 + (lane%4)*2, +1), b1 = rows +8; col(oc) = n*8 + lane/4
  for (int i = t; i < 4608; i += 256) {
    int lane = i & 31, kn = i >> 5;
    int n = kn & 7, k = kn >> 3;
    int gg = lane >> 2, tt2 = (lane & 3) * 2;
    int oc = n * 8 + gg;
    float qv[4];
    #pragma unroll
    for (int j = 0; j < 4; j++) {
      int K = k * 16 + tt2 + (j >> 1) * 8 + (j & 1);
      int tap = K >> 5, ic = K & 31;
      int kh = tap / 3, kw = tap % 3;
      qv[j] = (float)clamp_i((int)rintf(w2[((oc * 32 + ic) * 3 + kh) * 3 + kw] / sw2), -8, 7);
    }
    __half2 h0 = __floats2half2_rn(qv[0], qv[1]);
    __half2 h1 = __floats2half2_rn(qv[2], qv[3]);
    uint2 val;
    val.x = *(unsigned*)&h0;
    val.y = *(unsigned*)&h1;
    g_w2frag[i] = val;
  }
  for (int i = t; i < 128 * 64; i += 256)
    g_wf1q[i] = (signed char)clamp_i((int)rintf(wf1[i] / swf1), -8, 7);
  for (int i = t; i < 10 * 128; i += 256)
    g_wf2q[i] = (signed char)clamp_i((int)rintf(wf2[i] / swf2), -8, 7);
}

// ================= K3: quantize x -> packed int8 ===========================
__global__ void k_quant_x(const float* __restrict__ x) {
  int i = blockIdx.x * blockDim.x + threadIdx.x;
  if (i >= 32 * 224 * 224) return;
  int b = i / 50176, hw = i % 50176;
  float s = g_s.s_in;
  unsigned v = 0;
  #pragma unroll
  for (int c = 0; c < 3; c++) {
    float xv = x[(b * 3 + c) * 50176 + hw];
    int q = clamp_i((int)rintf(xv / s), -8, 7);
    v |= ((unsigned)(q & 0xff)) << (8 * c);
  }
  g_qx[i] = v;
}

// ================= K4: conv1 (dp4a) -> y1 int16 NHWC =======================
__global__ void __launch_bounds__(256) k_conv1() {
  __shared__ int   s_in[340];
  __shared__ uint4 s_w[18];
  const int bz = blockIdx.z;
  const int b = bz >> 2, ocg = bz & 3;
  const int h0 = blockIdx.y * 8, w0 = blockIdx.x * 32;
  const int t = threadIdx.x;

  if (t < 18)
    s_w[t] = *(const uint4*)&g_w1p[(t >> 1) * 32 + ocg * 8 + (t & 1) * 4];
  for (int i = t; i < 340; i += 256) {
    int row = i / 34, col = i % 34;
    int h = h0 + row, w = w0 + col;
    int v = 0;
    if (h < 224 && w < 224) v = (int)g_qx[(b * 224 + h) * 224 + w];
    s_in[i] = v;
  }
  __syncthreads();

  const int ty = t >> 5, tx = t & 31;
  int acc[8];
  #pragma unroll
  for (int k = 0; k < 8; k++) acc[k] = g_b1i[ocg * 8 + k];

  #pragma unroll
  for (int kh = 0; kh < 3; kh++) {
    #pragma unroll
    for (int kw = 0; kw < 3; kw++) {
      int a = s_in[(ty + kh) * 34 + tx + kw];
      uint4 wa = s_w[(kh * 3 + kw) * 2];
      uint4 wb = s_w[(kh * 3 + kw) * 2 + 1];
      acc[0] = __dp4a(a, (int)wa.x, acc[0]);
      acc[1] = __dp4a(a, (int)wa.y, acc[1]);
      acc[2] = __dp4a(a, (int)wa.z, acc[2]);
      acc[3] = __dp4a(a, (int)wa.w, acc[3]);
      acc[4] = __dp4a(a, (int)wb.x, acc[4]);
      acc[5] = __dp4a(a, (int)wb.y, acc[5]);
      acc[6] = __dp4a(a, (int)wb.z, acc[6]);
      acc[7] = __dp4a(a, (int)wb.w, acc[7]);
    }
  }

  const int oh = h0 + ty, ow = w0 + tx;
  int mloc = 0;
  if (oh < 222 && ow < 222) {
    unsigned p0 = (acc[0] & 0xffff) | ((unsigned)acc[1] << 16);
    unsigned p1 = (acc[2] & 0xffff) | ((unsigned)acc[3] << 16);
    unsigned p2 = (acc[4] & 0xffff) | ((unsigned)acc[5] << 16);
    unsigned p3 = (acc[6] & 0xffff) | ((unsigned)acc[7] << 16);
    *(uint4*)&g_y1[(size_t)((b * 222 + oh) * 222 + ow) * 32 + ocg * 8] = make_uint4(p0, p1, p2, p3);
    #pragma unroll
    for (int k = 0; k < 8; k++) mloc = max(mloc, acc[k]);
  }
  mloc = __reduce_max_sync(0xffffffffu, mloc);
  __shared__ int smx[8];
  if ((t & 31) == 0) smx[t >> 5] = mloc;
  __syncthreads();
  if (t == 0) {
    int m = smx[0];
    #pragma unroll
    for (int i = 1; i < 8; i++) m = max(m, smx[i]);
    atomicMax(&g_max1arr[(blockIdx.x + 7 * (blockIdx.y + 28 * blockIdx.z)) & 255], m);
  }
}

// ================= K5: scales after conv1 ==================================
__global__ void k_scales1(const float* __restrict__ b2) {
  const int t = threadIdx.x;
  int v = g_max1arr[t];
  v = __reduce_max_sync(0xffffffffu, v);
  __shared__ int   smx[8];
  __shared__ float sc[2];
  if ((t & 31) == 0) smx[t >> 5] = v;
  __syncthreads();
  if (t == 0) {
    int mm = smx[0];
    #pragma unroll
    for (int i = 1; i < 8; i++) mm = max(mm, smx[i]);
    float S1 = g_s.S1;
    float my = fmaxf((float)mm * S1, 1e-8f);
    float s1 = my / 15.0f;
    g_s.max1 = mm; g_s.s1 = s1;
    g_s.f1 = 15.0f * S1 / my;
    float S2 = s1 * g_s.sw2;
    g_s.S2 = S2;
    sc[0] = s1; sc[1] = g_s.sw2;
  }
  __syncthreads();
  if (t < 64) g_b2i[t] = (int)rintf(b2[t] / (sc[0] * sc[1]));
}

// ================= K6: quantize y1 -> q1 fp16 (exact small ints) ===========
__global__ void k_quant_y1() {
  unsigned i = blockIdx.x * blockDim.x + threadIdx.x;   // 8 values per thread
  if (i >= 50466816u / 8u) return;
  const float f1 = g_s.f1;
  uint4 v = ((const uint4*)g_y1)[i];
  int a0 = (short)(v.x & 0xffff), a1 = (short)(v.x >> 16);
  int a2 = (short)(v.y & 0xffff), a3 = (short)(v.y >> 16);
  int a4 = (short)(v.z & 0xffff), a5 = (short)(v.z >> 16);
  int a6 = (short)(v.w & 0xffff), a7 = (short)(v.w >> 16);
  float q0 = (float)clamp_i((int)rintf((float)a0 * f1), 0, 15);
  float q1 = (float)clamp_i((int)rintf((float)a1 * f1), 0, 15);
  float q2 = (float)clamp_i((int)rintf((float)a2 * f1), 0, 15);
  float q3 = (float)clamp_i((int)rintf((float)a3 * f1), 0, 15);
  float q4 = (float)clamp_i((int)rintf((float)a4 * f1), 0, 15);
  float q5 = (float)clamp_i((int)rintf((float)a5 * f1), 0, 15);
  float q6 = (float)clamp_i((int)rintf((float)a6 * f1), 0, 15);
  float q7 = (float)clamp_i((int)rintf((float)a7 * f1), 0, 15);
  __half2 h0 = __floats2half2_rn(q0, q1);
  __half2 h1 = __floats2half2_rn(q2, q3);
  __half2 h2 = __floats2half2_rn(q4, q5);
  __half2 h3 = __floats2half2_rn(q6, q7);
  uint4 o;
  o.x = *(unsigned*)&h0; o.y = *(unsigned*)&h1;
  o.z = *(unsigned*)&h2; o.w = *(unsigned*)&h3;
  ((uint4*)g_q1h)[i] = o;
}

// ========== K7: conv2 via mma.sync fp16 HMMA (implicit GEMM) ===============
// Tile: 64 pixels (2 rows x 32 cols) x 64 oc, K=288 (18 chunks of k16).
// A fp16 im2col in smem [64 rows][296 el] (stride 148 words, conflict-free).
// B fragments streamed from global (L1-resident, 36.9 KB).
// Warp (w): m-chunk = w&3 (16 pixels), n-half = w>>2 (4 n-chunks of 8 oc).
static constexpr int TILES_TOTAL = 32 * 110 * 7;   // 24640
static constexpr int TPB = 5;
static constexpr int CONV2_GRID = TILES_TOTAL / TPB;  // 4928

__global__ void __launch_bounds__(256) k_conv2mma() {
  __shared__ __align__(16) unsigned s_A[64 * 148];   // fp16 A tile (37888 B)
  __shared__ __align__(16) uint2 s_patch[4 * 34 * 8]; // raw fp16 patch (8704 B)
  __shared__ float s_bias[64];
  __shared__ int s_red[8];

  const int t = threadIdx.x;
  const int wid = t >> 5, lane = t & 31;
  const int g = lane >> 2, t2 = (lane & 3) * 2;
  const int mq = wid & 3, nh = wid >> 2;
  __half* s_stage = (__half*)s_A;                    // epilogue overlay

  if (t < 64) s_bias[t] = (float)g_b2i[t];

  float mloc = 0.f;

  for (int it = 0; it < TPB; it++) {
    const int T = blockIdx.x * TPB + it;
    const int b = T / 770;
    const int rem = T - b * 770;
    const int rt = rem / 7, ct = rem % 7;
    const int h0 = rt * 2, w0 = ct * 32;

    // ---- patch: 4 rows x 34 cols x 32 fp16 (64B/pixel), 544 uint4 --------
    __syncthreads();   // protect s_A/s_patch from previous iteration readers
    for (int i = t; i < 544; i += 256) {
      int pix = i >> 2, q = i & 3;
      int r = pix / 34, c = pix % 34;
      int w = w0 + c;
      uint4 v = make_uint4(0, 0, 0, 0);
      if (w < 222)
        v = ((const uint4*)(g_q1h + ((size_t)(b * 222 + h0 + r) * 222 + w) * 32))[q];
      ((uint4*)s_patch)[i] = v;
    }
    __syncthreads();

    // ---- A build: 64 rows x 72 uint2 (pure copies) -----------------------
    for (int i = t; i < 4608; i += 256) {
      int p = i / 72, w2i = i - p * 72;
      int pr = p >> 5, pc = p & 31;
      int tap = w2i >> 3, cc2 = w2i & 7;
      int kh = tap / 3, kw = tap - kh * 3;
      ((uint2*)s_A)[p * 74 + w2i] = s_patch[((pr + kh) * 34 + pc + kw) * 8 + cc2];
    }
    __syncthreads();

    // ---- mma mainloop ----------------------------------------------------
    float acc[4][4];
    #pragma unroll
    for (int n = 0; n < 4; n++)
      acc[n][0] = acc[n][1] = acc[n][2] = acc[n][3] = 0.f;

    const unsigned* Abase = s_A + (mq * 16 + g) * 148 + (lane & 3);
    #pragma unroll
    for (int k = 0; k < 18; k++) {
      unsigned a0 = Abase[k * 8];
      unsigned a1 = Abase[8 * 148 + k * 8];
      unsigned a2 = Abase[k * 8 + 4];
      unsigned a3 = Abase[8 * 148 + k * 8 + 4];
      #pragma unroll
      for (int n = 0; n < 4; n++) {
        uint2 bb = g_w2frag[(k * 8 + nh * 4 + n) * 32 + lane];
        asm volatile(
          "mma.sync.aligned.m16n8k16.row.col.f32.f16.f16.f32 "
          "{%0,%1,%2,%3}, {%4,%5,%6,%7}, {%8,%9}, {%0,%1,%2,%3};"
          : "+f"(acc[n][0]), "+f"(acc[n][1]), "+f"(acc[n][2]), "+f"(acc[n][3])
          : "r"(a0), "r"(a1), "r"(a2), "r"(a3), "r"(bb.x), "r"(bb.y));
      }
    }
    __syncthreads();   // all warps done reading s_A before staging overlay

    // ---- epilogue: bias, exact max (f32), stage fp16 ---------------------
    const int p0 = mq * 16 + g, p1 = p0 + 8;
    const bool ok0 = (w0 + (p0 & 31)) < 220;
    const bool ok1 = (w0 + (p1 & 31)) < 220;
    #pragma unroll
    for (int n = 0; n < 4; n++) {
      int oc = (nh * 4 + n) * 8 + t2;
      float v0 = acc[n][0] + s_bias[oc];
      float v1 = acc[n][1] + s_bias[oc + 1];
      float v2 = acc[n][2] + s_bias[oc];
      float v3 = acc[n][3] + s_bias[oc + 1];
      if (ok0) mloc = fmaxf(mloc, fmaxf(v0, v1));
      if (ok1) mloc = fmaxf(mloc, fmaxf(v2, v3));
      *(__half2*)&s_stage[p0 * 66 + oc] = __floats2half2_rn(v0, v1);
      *(__half2*)&s_stage[p1 * 66 + oc] = __floats2half2_rn(v2, v3);
    }
    __syncthreads();

    // ---- coalesced write-out: 2048 pixel-pairs ---------------------------
    for (int i = t; i < 2048; i += 256) {
      int oc = i >> 5, pp = (i & 31) * 2;
      int ow = w0 + (pp & 31);
      if (ow < 220) {
        int oh = h0 + (pp >> 5);
        unsigned lo = __half_as_ushort(s_stage[pp * 66 + oc]);
        unsigned hi = __half_as_ushort(s_stage[(pp + 1) * 66 + oc]);
        *(unsigned*)&g_y2h[((size_t)(b * 64 + oc) * 48400) + oh * 220 + ow] =
            lo | (hi << 16);
      }
    }
  }

  // ---- block max -> hashed float-bits atomic -----------------------------
  #pragma unroll
  for (int o = 16; o; o >>= 1) mloc = fmaxf(mloc, __shfl_xor_sync(0xffffffffu, mloc, o));
  if ((t & 31) == 0) s_red[wid] = __float_as_int(mloc);
  __syncthreads();
  if (t == 0) {
    int m = s_red[0];
    #pragma unroll
    for (int i = 1; i < 8; i++) m = max(m, s_red[i]);
    atomicMax(&g_max2arr[blockIdx.x & 255], m);
  }
}

// ================= K7.5: scales after conv2 ================================
__global__ void k_scales2() {
  const int t = threadIdx.x;
  int v = g_max2arr[t];
  v = __reduce_max_sync(0xffffffffu, v);
  __shared__ int smx[8];
  if ((t & 31) == 0) smx[t >> 5] = v;
  __syncthreads();
  if (t == 0) {
    int mm = smx[0];
    #pragma unroll
    for (int i = 1; i < 8; i++) mm = max(mm, smx[i]);
    float maxf = __int_as_float(mm);      // nonneg: int-max == float-max
    float S2 = g_s.S2;
    float my = fmaxf(maxf * S2, 1e-8f);
    g_s.s2 = my / 15.0f;
    g_s.r2 = 15.0f * S2 / my;
  }
}

// ================= K8: quantize y2 (fp16) + avg-pool =======================
__global__ void __launch_bounds__(256) k_pool() {
  const int bc = blockIdx.x;
  const uint4* __restrict__ p = (const uint4*)(g_y2h + (size_t)bc * 48400);
  const float r2 = g_s.r2;
  int s = 0;
  for (int i = threadIdx.x; i < 6050; i += 256) {
    uint4 v = p[i];
    const __half2* h = (const __half2*)&v;
    #pragma unroll
    for (int j = 0; j < 4; j++) {
      float2 f = __half22float2(h[j]);
      s += clamp_i((int)rintf(f.x * r2), 0, 15);
      s += clamp_i((int)rintf(f.y * r2), 0, 15);
    }
  }
  s = __reduce_add_sync(0xffffffffu, s);
  __shared__ int sm[8];
  if ((threadIdx.x & 31) == 0) sm[threadIdx.x >> 5] = s;
  __syncthreads();
  if (threadIdx.x == 0) {
    int r = 0;
    #pragma unroll
    for (int i = 0; i < 8; i++) r += sm[i];
    g_pool[bc] = r;
  }
}

// ================= K9: head ================================================
__global__ void __launch_bounds__(256) k_head(const float* __restrict__ bf1,
                                              const float* __restrict__ bf2,
                                              float* __restrict__ out) {
  __shared__ float mean[32 * 64];
  __shared__ float y3[32 * 128];
  __shared__ float y4[320];
  __shared__ float red[8];
  __shared__ float s3sh;
  const int t = threadIdx.x;

  const float s2 = g_s.s2;
  const float swf1 = g_s.swf1, swf2 = g_s.swf2;
  const float msc = s2 / 48400.0f;
  for (int i = t; i < 2048; i += 256) mean[i] = (float)g_pool[i] * msc;
  __syncthreads();

  float lmax = 0.f;
  for (int idx = t; idx < 4096; idx += 256) {
    int b = idx >> 7, o = idx & 127;
    const signed char* wr = &g_wf1q[o * 64];
    const float* mr = &mean[b * 64];
    float a = 0.f;
    #pragma unroll 8
    for (int c = 0; c < 64; c++) a += mr[c] * (float)wr[c];
    float bq = rintf(bf1[o] / (s2 * swf1)) * (s2 * swf1);
    float y = swf1 * a + bq;
    y3[idx] = y;
    lmax = fmaxf(lmax, y);
  }
  #pragma unroll
  for (int o = 16; o; o >>= 1) lmax = fmaxf(lmax, __shfl_xor_sync(0xffffffffu, lmax, o));
  if ((t & 31) == 0) red[t >> 5] = lmax;
  __syncthreads();
  if (t == 0) {
    float r = red[0];
    #pragma unroll
    for (int i = 1; i < 8; i++) r = fmaxf(r, red[i]);
    s3sh = fmaxf(r, 1e-8f) / 15.0f;
  }
  __syncthreads();
  const float s3 = s3sh;

  for (int idx = t; idx < 320; idx += 256) {
    int b = idx / 10, k = idx % 10;
    const signed char* wr = &g_wf2q[k * 128];
    const float* yr = &y3[b * 128];
    float a = 0.f;
    #pragma unroll 8
    for (int o = 0; o < 128; o++) {
      int q = clamp_i((int)rintf(yr[o] / s3), 0, 15);
      a += (float)q * (float)wr[o];
    }
    float bq = rintf(bf2[k] / (s3 * swf2)) * (s3 * swf2);
    y4[idx] = s3 * swf2 * a + bq;
  }
  __syncthreads();

  if (t < 32) {
    float mval = -1e30f;
    #pragma unroll
    for (int k = 0; k < 10; k++) mval = fmaxf(mval, y4[t * 10 + k]);
    float ssum = 0.f;
    #pragma unroll
    for (int k = 0; k < 10; k++) ssum += expf(y4[t * 10 + k] - mval);
    float l = logf(ssum);
    #pragma unroll
    for (int k = 0; k < 10; k++) out[t * 10 + k] = y4[t * 10 + k] - mval - l;
  }
}

// ============================= launcher ====================================
extern "C" void kernel_launch(void* const* d_in, const int* in_sizes, int n_in,
                              void* d_out, int out_size) {
  const float* x   = (const float*)d_in[0];
  const float* w1  = (const float*)d_in[1];
  const float* b1  = (const float*)d_in[2];
  const float* w2  = (const float*)d_in[3];
  const float* b2  = (const float*)d_in[4];
  const float* wf1 = (const float*)d_in[5];
  const float* bf1 = (const float*)d_in[6];
  const float* wf2 = (const float*)d_in[7];
  const float* bf2 = (const float*)d_in[8];
  float* out = (float*)d_out;

  k_init<<<1, 256>>>();
  k_absmax_x<<<2048, 256>>>(x, 32 * 3 * 224 * 224);
  k_prep<<<1, 256>>>(w1, b1, w2, wf1, wf2);
  k_quant_x<<<(32 * 224 * 224 + 255) / 256, 256>>>(x);
  k_conv1<<<dim3(7, 28, 128), 256>>>();
  k_scales1<<<1, 256>>>(b2);
  k_quant_y1<<<(50466816 / 8 + 255) / 256, 256>>>();
  k_conv2mma<<<CONV2_GRID, 256>>>();
  k_scales2<<<1, 256>>>();
  k_pool<<<2048, 256>>>();
  k_head<<<1, 256>>>(bf1, bf2, out);
}